// round 2
// baseline (speedup 1.0000x reference)
#include <cuda_runtime.h>
#include <cuda_bf16.h>

// Problem constants (shapes fixed by the dataset)
#define LL      4
#define NN      50000
#define DD      64
#define HIDN    256
#define KDIM    512        // L * 2 * D
#define TILE_E  64
#define NTHREADS 256

// A region: 64 rows x 513 floats (padded). Reused as X (64 x 257) in epilogue.
#define A_STRIDE 513
#define X_STRIDE 257
#define A_FLOATS (TILE_E * A_STRIDE)
// smem layout (floats): A | gamma(256) | beta(256) | w3(256) | b1(256) | sidx(64 int) | didx(64 int)
#define SMEM_FLOATS (A_FLOATS + 4 * HIDN + (2 * TILE_E))
#define SMEM_BYTES  (SMEM_FLOATS * 4)

// Pre-transposed W1: W1T[k][j] = W1[j][k]  (512 x 256 fp32 = 512 KB, L2-resident)
__device__ float g_W1T[KDIM * HIDN];

__global__ void transpose_w1_kernel(const float* __restrict__ W1) {
    int i = blockIdx.x * blockDim.x + threadIdx.x;
    if (i < KDIM * HIDN) {
        int k = i / HIDN;
        int j = i - k * HIDN;
        g_W1T[i] = W1[j * KDIM + k];
    }
}

__global__ __launch_bounds__(NTHREADS, 1)
void fused_edge_mlp_kernel(const float* __restrict__ h_all,
                           const int*   __restrict__ src,
                           const int*   __restrict__ dst,
                           const float* __restrict__ b1,
                           const float* __restrict__ W3,
                           const float* __restrict__ b3,
                           const float* __restrict__ gamma2,
                           const float* __restrict__ beta2,
                           float* __restrict__ out,
                           int E) {
    extern __shared__ float sh[];
    float* A    = sh;                       // 64 x 513
    float* gs   = sh + A_FLOATS;            // gamma  256
    float* bes  = gs + HIDN;                // beta   256
    float* w3s  = bes + HIDN;               // W3 row 256
    float* b1s  = w3s + HIDN;               // b1     256
    int*   sidx = (int*)(b1s + HIDN);       // 64
    int*   didx = sidx + TILE_E;            // 64

    const int tid    = threadIdx.x;
    const int e_base = blockIdx.x * TILE_E;

    if (tid < TILE_E) {
        int eg = e_base + tid;
        if (eg >= E) eg = E - 1;            // clamp tail (store is guarded later)
        sidx[tid] = src[eg];
        didx[tid] = dst[eg];
    }
    if (tid < HIDN) {
        gs[tid]  = gamma2[tid];
        bes[tid] = beta2[tid];
        w3s[tid] = W3[tid];
        b1s[tid] = b1[tid];
    }
    __syncthreads();

    // imp = (l+1)/sum(1..L) = (l+1)/10
    const float imp[LL] = {0.1f, 0.2f, 0.3f, 0.4f};

    // ---- Phase 1: gather + scale + tanh into shared A[e][k] ----
    // feature k = l*128 + half*64 + c ; half 0 -> src row, half 1 -> dst row
    #pragma unroll 4
    for (int i = tid; i < TILE_E * KDIM; i += NTHREADS) {
        int e = i >> 9;                     // /512
        int k = i & (KDIM - 1);
        int l = k >> 7;
        int c = k & 63;
        int idx = ((k >> 6) & 1) ? didx[e] : sidx[e];
        float v = h_all[l * (NN * DD) + idx * DD + c];
        A[e * A_STRIDE + k] = tanhf(v * imp[l]);
    }
    __syncthreads();

    // ---- Phase 2: X[64][256] = A[64][512] @ W1T ; 8x8 register tile/thread ----
    const int lane = tid & 31;
    const int wid  = tid >> 5;
    const int er   = lane & 7;              // edge group within warp
    const int jg   = lane >> 3;             // j group within warp
    const int e0   = er * 8;
    const int j0   = (wid * 4 + jg) * 8;

    float acc[8][8];
    #pragma unroll
    for (int i = 0; i < 8; ++i)
        #pragma unroll
        for (int j = 0; j < 8; ++j) acc[i][j] = 0.f;

    const float4* Wt = reinterpret_cast<const float4*>(g_W1T);
    #pragma unroll 2
    for (int k = 0; k < KDIM; ++k) {
        int wbase = (k * HIDN + j0) >> 2;
        float4 w0 = Wt[wbase];
        float4 w1 = Wt[wbase + 1];
        float wv[8] = {w0.x, w0.y, w0.z, w0.w, w1.x, w1.y, w1.z, w1.w};
        float av[8];
        #pragma unroll
        for (int i = 0; i < 8; ++i) av[i] = A[(e0 + i) * A_STRIDE + k];
        #pragma unroll
        for (int i = 0; i < 8; ++i)
            #pragma unroll
            for (int j = 0; j < 8; ++j)
                acc[i][j] = fmaf(av[i], wv[j], acc[i][j]);
    }
    __syncthreads();   // everyone done reading A before we overwrite it as X

    // ---- Phase 3: X = acc + b1 staged in shared (alias of A region) ----
    float* X = sh;     // 64 x 257, fits inside A region (16448 < 32832 floats)
    #pragma unroll
    for (int i = 0; i < 8; ++i)
        #pragma unroll
        for (int j = 0; j < 8; ++j)
            X[(e0 + i) * X_STRIDE + j0 + j] = acc[i][j] + b1s[j0 + j];
    __syncthreads();

    // ---- Phase 4: per-edge LayerNorm + ReLU + dot(W3) ; warp w owns 8 edges ----
    const float b3v = b3[0];
    #pragma unroll
    for (int s = 0; s < 8; ++s) {
        int e = wid * 8 + s;
        float v[8];
        float sum = 0.f, sq = 0.f;
        #pragma unroll
        for (int i = 0; i < 8; ++i) {
            v[i] = X[e * X_STRIDE + lane + 32 * i];
            sum += v[i];
            sq  = fmaf(v[i], v[i], sq);
        }
        #pragma unroll
        for (int off = 16; off > 0; off >>= 1) {
            sum += __shfl_xor_sync(0xffffffffu, sum, off);
            sq  += __shfl_xor_sync(0xffffffffu, sq, off);
        }
        float mu  = sum * (1.f / 256.f);
        float var = sq * (1.f / 256.f) - mu * mu;
        float rs  = rsqrtf(var + 1e-5f);
        float p = 0.f;
        #pragma unroll
        for (int i = 0; i < 8; ++i) {
            int j = lane + 32 * i;
            float y = (v[i] - mu) * rs * gs[j] + bes[j];
            y = fmaxf(y, 0.f);
            p = fmaf(y, w3s[j], p);
        }
        #pragma unroll
        for (int off = 16; off > 0; off >>= 1)
            p += __shfl_xor_sync(0xffffffffu, p, off);
        if (lane == 0) {
            int eg = e_base + e;
            if (eg < E) out[eg] = p + b3v;
        }
    }
}

extern "C" void kernel_launch(void* const* d_in, const int* in_sizes, int n_in,
                              void* d_out, int out_size) {
    const float* h_all  = (const float*)d_in[0];
    const int*   src    = (const int*)  d_in[1];
    const int*   dst    = (const int*)  d_in[2];
    const float* W1     = (const float*)d_in[3];
    const float* b1     = (const float*)d_in[4];
    const float* W3     = (const float*)d_in[5];
    const float* b3     = (const float*)d_in[6];
    const float* gamma2 = (const float*)d_in[7];
    const float* beta2  = (const float*)d_in[8];
    float* out = (float*)d_out;

    const int E = in_sizes[1];

    // >48KB dynamic smem needs the opt-in attribute. Not a stream op; safe
    // during graph capture (executes immediately), idempotent per call.
    cudaFuncSetAttribute(fused_edge_mlp_kernel,
                         cudaFuncAttributeMaxDynamicSharedMemorySize,
                         SMEM_BYTES);

    transpose_w1_kernel<<<(KDIM * HIDN + 255) / 256, 256>>>(W1);

    int nb = (E + TILE_E - 1) / TILE_E;
    fused_edge_mlp_kernel<<<nb, NTHREADS, SMEM_BYTES>>>(
        h_all, src, dst, b1, W3, b3, gamma2, beta2, out, E);
}

// round 5
// speedup vs baseline: 5.3057x; 5.3057x over previous
#include <cuda_runtime.h>
#include <cstdint>

// ---------------- problem constants ----------------
#define NNODES 50000
#define DHEAD  64
#define HIDN   256
#define KDIM   512
#define TILE_E 128           // edges per CTA
#define NTH    512           // 16 warps: 4 m-groups x 4 n-groups, warp tile 32x64
#define NCHUNK 16
#define KC     32            // K per chunk
#define BCHUNK_FLOATS 8192   // 256 n * 32 k
#define ACHUNK_FLOATS 4096   // 128 m * 32 k

// ---------------- smem layout (bytes) ----------------
#define SM_SIDX  0                 // 128 ints
#define SM_DIDX  512
#define SM_B1    1024              // 256 f each
#define SM_G     2048
#define SM_BE    3072
#define SM_W3    4096
#define SM_SSUM  5120              // [4][128] f
#define SM_SSQ   7168
#define SM_SDOT  9216
#define SM_MUS   11264             // 128 f
#define SM_RSS   11776
#define SM_STAGE 12288             // 16B aligned
#define STAGE_SZ 49152             // A 16KB + B 32KB
#define SM_A(s)  (SM_STAGE + (s) * STAGE_SZ)
#define SM_B(s)  (SM_A(s) + 16384)
#define SMEM_TOTAL (SM_STAGE + 2 * STAGE_SZ)   // 110592

// W1 pre-packed into per-chunk mma-fragment order, RN-rounded to tf32.
__device__ float g_Bpack[NCHUNK * BCHUNK_FLOATS];   // 512 KB

// ---------------- helpers ----------------
__device__ __forceinline__ uint32_t smem_u32(const void* p) {
    uint32_t a;
    asm("{ .reg .u64 t; cvta.to.shared.u64 t, %1; cvt.u32.u64 %0, t; }" : "=r"(a) : "l"(p));
    return a;
}
__device__ __forceinline__ uint32_t f2tf32(float f) {
    uint32_t u;
    asm("cvt.rna.tf32.f32 %0, %1;" : "=r"(u) : "f"(f));
    return u;
}
__device__ __forceinline__ float tanh_fast(float x) {
    float r;
    asm("tanh.approx.f32 %0, %1;" : "=f"(r) : "f"(x));
    return r;
}
__device__ __forceinline__ void cp16(uint32_t dst, const void* src) {
    asm volatile("cp.async.ca.shared.global [%0], [%1], 16;" :: "r"(dst), "l"(src));
}
__device__ __forceinline__ void cp_commit() {
    asm volatile("cp.async.commit_group;" ::: "memory");
}
template <int N>
__device__ __forceinline__ void cp_wait() {
    asm volatile("cp.async.wait_group %0;" :: "n"(N) : "memory");
}
__device__ __forceinline__ void mma_tf32(float* c, const uint32_t* a, uint32_t b0, uint32_t b1) {
    asm volatile(
        "mma.sync.aligned.m16n8k8.row.col.f32.tf32.tf32.f32 "
        "{%0,%1,%2,%3}, {%4,%5,%6,%7}, {%8,%9}, {%0,%1,%2,%3};"
        : "+f"(c[0]), "+f"(c[1]), "+f"(c[2]), "+f"(c[3])
        : "r"(a[0]), "r"(a[1]), "r"(a[2]), "r"(a[3]), "r"(b0), "r"(b1));
}

// ---------------- W1 prep: tf32-round + fragment pack ----------------
// B fragment (m16n8k8.row.col, B col-major): for element (n, k) of a chunk:
//   ngroup=n>>6, ntile=(n>>3)&7, nn=n&7 ; ktile=kc>>3, kk=kc&7
//   lane=(nn<<2)|(kk&3) ; bidx=kk>>2 ; kp=ktile>>1 ; fi=((ktile&1)<<1)|bidx
//   float4 per lane = frags of two consecutive k-tiles.
__global__ void prep_w1(const float* __restrict__ W1) {
    int i = blockIdx.x * blockDim.x + threadIdx.x;
    if (i >= HIDN * KDIM) return;
    int n = i >> 9;
    int k = i & 511;
    int c = k >> 5, kc = k & 31;
    int ngroup = n >> 6, ntile = (n >> 3) & 7, nn = n & 7;
    int ktile = kc >> 3, kk = kc & 7;
    int lane = (nn << 2) | (kk & 3);
    int kp = ktile >> 1;
    int fi = ((ktile & 1) << 1) | (kk >> 2);
    int off = ((((ngroup * 8 + ntile) * 2 + kp) * 32 + lane) << 2) + fi;
    g_Bpack[c * BCHUNK_FLOATS + off] = __uint_as_float(f2tf32(W1[i]));
}

// ---------------- fused kernel ----------------
__global__ __launch_bounds__(NTH, 1)
void fused_edge_mlp_mma(const float* __restrict__ h_all,
                        const int*   __restrict__ src,
                        const int*   __restrict__ dst,
                        const float* __restrict__ b1,
                        const float* __restrict__ W3,
                        const float* __restrict__ b3,
                        const float* __restrict__ gamma2,
                        const float* __restrict__ beta2,
                        float* __restrict__ out,
                        int E) {
    extern __shared__ char smem[];
    const uint32_t sb = smem_u32(smem);

    const int tid  = threadIdx.x;
    const int wid  = tid >> 5;
    const int lane = tid & 31;
    const int mg   = wid >> 2;      // m-group: rows mg*32 .. +31
    const int ng   = wid & 3;       // n-group: cols ng*64 .. +63
    const int e_base = blockIdx.x * TILE_E;

    int*   sidx = (int*)(smem + SM_SIDX);
    int*   didx = (int*)(smem + SM_DIDX);
    float* b1s  = (float*)(smem + SM_B1);
    float* gs   = (float*)(smem + SM_G);
    float* bes  = (float*)(smem + SM_BE);
    float* w3s  = (float*)(smem + SM_W3);
    float* ssum = (float*)(smem + SM_SSUM);
    float* ssq  = (float*)(smem + SM_SSQ);
    float* sdot = (float*)(smem + SM_SDOT);
    float* mus  = (float*)(smem + SM_MUS);
    float* rss  = (float*)(smem + SM_RSS);

    if (tid < TILE_E) {
        int eg = e_base + tid;
        if (eg >= E) eg = E - 1;
        sidx[tid] = src[eg];
        didx[tid] = dst[eg];
    }
    if (tid < HIDN) {
        b1s[tid] = b1[tid];
        gs[tid]  = gamma2[tid];
        bes[tid] = beta2[tid];
        w3s[tid] = W3[tid];
    }
    __syncthreads();

    // accumulators: warp tile 32x64 -> acc[mtile][ntile][4]
    float acc[2][8][4];
    #pragma unroll
    for (int mt = 0; mt < 2; ++mt)
        #pragma unroll
        for (int nt = 0; nt < 8; ++nt)
            #pragma unroll
            for (int j = 0; j < 4; ++j) acc[mt][nt][j] = 0.f;

    // --- prefetch chunk 0: B via cp.async, A via LDG into regs ---
    {
        const float* bsrc = g_Bpack;
        #pragma unroll
        for (int i = 0; i < 4; ++i)
            cp16(sb + SM_B(0) + (i * NTH + tid) * 16, bsrc + (i * NTH + tid) * 4);
        cp_commit();
    }
    float4 pa[2];
    {
        // chunk 0: l=0, half=0 (src), cc0=0
        const float* hb = h_all;
        #pragma unroll
        for (int i = 0; i < 2; ++i) {
            int f = i * NTH + tid;
            int e = f >> 3, q = f & 7;
            pa[i] = *(const float4*)(hb + (size_t)sidx[e] * DHEAD + q * 4);
        }
    }

    #pragma unroll 1
    for (int c = 0; c < NCHUNK; ++c) {
        const int b = c & 1;

        // ---- store A chunk c (tanh + tf32-round + fragment-order STS) ----
        {
            const int l = c >> 2;
            const float im = 0.1f * (float)(l + 1);
            #pragma unroll
            for (int i = 0; i < 2; ++i) {
                int f = i * NTH + tid;
                int e = f >> 3, q = f & 7;
                uint32_t t0 = f2tf32(tanh_fast(pa[i].x * im));
                uint32_t t1 = f2tf32(tanh_fast(pa[i].y * im));
                uint32_t t2 = f2tf32(tanh_fast(pa[i].z * im));
                uint32_t t3 = f2tf32(tanh_fast(pa[i].w * im));
                int mgroup = e >> 5, mtile = (e >> 4) & 1, r = e & 15;
                int ktile = q >> 1;
                int aidx  = ((q & 1) << 1) | (r >> 3);
                int base  = (((mgroup * 2 + mtile) * 4 + ktile) * 32 + ((r & 7) << 2)) * 4 + aidx;
                uint32_t* dstp = (uint32_t*)(smem + SM_A(b));
                dstp[base + 0]  = t0;
                dstp[base + 4]  = t1;
                dstp[base + 8]  = t2;
                dstp[base + 12] = t3;
            }
        }

        // ---- issue B cp.async for chunk c+1 ----
        if (c < NCHUNK - 1) {
            const float* bsrc = g_Bpack + (c + 1) * BCHUNK_FLOATS;
            #pragma unroll
            for (int i = 0; i < 4; ++i)
                cp16(sb + SM_B(b ^ 1) + (i * NTH + tid) * 16, bsrc + (i * NTH + tid) * 4);
            cp_commit();
            cp_wait<1>();   // chunk c's B has landed
        } else {
            cp_wait<0>();
        }
        __syncthreads();

        // ---- prefetch A chunk c+1 into regs (overlaps MMA below) ----
        if (c < NCHUNK - 1) {
            const int cn = c + 1;
            const int l = cn >> 2, half = (cn >> 1) & 1, cc0 = (cn & 1) * KC;
            const int* ip = half ? didx : sidx;
            const float* hb = h_all + (size_t)l * (NNODES * DHEAD) + cc0;
            #pragma unroll
            for (int i = 0; i < 2; ++i) {
                int f = i * NTH + tid;
                int e = f >> 3, q = f & 7;
                pa[i] = *(const float4*)(hb + (size_t)ip[e] * DHEAD + q * 4);
            }
        }

        // ---- MMA on chunk c ----
        {
            const char* Ab = smem + SM_A(b);
            const char* Bb = smem + SM_B(b);
            #pragma unroll
            for (int kp = 0; kp < 2; ++kp) {
                uint4 bb[8];
                #pragma unroll
                for (int nt = 0; nt < 8; ++nt)
                    bb[nt] = *(const uint4*)(Bb + ((((ng * 8 + nt) * 2 + kp) * 32 + lane) << 4));
                #pragma unroll
                for (int kt2 = 0; kt2 < 2; ++kt2) {
                    const int kt = kp * 2 + kt2;
                    uint4 aa[2];
                    #pragma unroll
                    for (int mt = 0; mt < 2; ++mt)
                        aa[mt] = *(const uint4*)(Ab + ((((mg * 2 + mt) * 4 + kt) * 32 + lane) << 4));
                    #pragma unroll
                    for (int mt = 0; mt < 2; ++mt)
                        #pragma unroll
                        for (int nt = 0; nt < 8; ++nt)
                            mma_tf32(acc[mt][nt], &aa[mt].x,
                                     kt2 ? bb[nt].z : bb[nt].x,
                                     kt2 ? bb[nt].w : bb[nt].y);
                }
            }
        }
        __syncthreads();
    }

    // ---------------- epilogue ----------------
    const int qr = lane >> 2;   // row within 8-row group
    const int ql = lane & 3;    // col pair selector

    // pass 1: bias + partial sum/sumsq per row (this warp's 64 cols)
    float sums[2][2] = {{0.f, 0.f}, {0.f, 0.f}};
    float sqs[2][2]  = {{0.f, 0.f}, {0.f, 0.f}};
    #pragma unroll
    for (int mt = 0; mt < 2; ++mt) {
        #pragma unroll
        for (int nt = 0; nt < 8; ++nt) {
            int colb = ng * 64 + nt * 8 + ql * 2;
            float b10 = b1s[colb], b11 = b1s[colb + 1];
            float v0 = acc[mt][nt][0] + b10;
            float v1 = acc[mt][nt][1] + b11;
            float v2 = acc[mt][nt][2] + b10;
            float v3 = acc[mt][nt][3] + b11;
            acc[mt][nt][0] = v0; acc[mt][nt][1] = v1;
            acc[mt][nt][2] = v2; acc[mt][nt][3] = v3;
            sums[mt][0] += v0 + v1;           sums[mt][1] += v2 + v3;
            sqs[mt][0] = fmaf(v0, v0, sqs[mt][0]); sqs[mt][0] = fmaf(v1, v1, sqs[mt][0]);
            sqs[mt][1] = fmaf(v2, v2, sqs[mt][1]); sqs[mt][1] = fmaf(v3, v3, sqs[mt][1]);
        }
    }
    #pragma unroll
    for (int off = 1; off <= 2; off <<= 1) {
        #pragma unroll
        for (int mt = 0; mt < 2; ++mt)
            #pragma unroll
            for (int ro = 0; ro < 2; ++ro) {
                sums[mt][ro] += __shfl_xor_sync(0xffffffffu, sums[mt][ro], off);
                sqs[mt][ro]  += __shfl_xor_sync(0xffffffffu, sqs[mt][ro], off);
            }
    }
    if (ql == 0) {
        #pragma unroll
        for (int mt = 0; mt < 2; ++mt)
            #pragma unroll
            for (int ro = 0; ro < 2; ++ro) {
                int row = mg * 32 + mt * 16 + ro * 8 + qr;
                ssum[ng * 128 + row] = sums[mt][ro];
                ssq[ng * 128 + row]  = sqs[mt][ro];
            }
    }
    __syncthreads();

    if (tid < 128) {
        float ts = ssum[tid] + ssum[128 + tid] + ssum[256 + tid] + ssum[384 + tid];
        float tq = ssq[tid]  + ssq[128 + tid]  + ssq[256 + tid]  + ssq[384 + tid];
        float mu  = ts * (1.f / 256.f);
        float var = tq * (1.f / 256.f) - mu * mu;
        mus[tid] = mu;
        rss[tid] = rsqrtf(var + 1e-5f);
    }
    __syncthreads();

    // pass 2: normalize + relu + W3 dot
    float dots[2][2] = {{0.f, 0.f}, {0.f, 0.f}};
    #pragma unroll
    for (int mt = 0; mt < 2; ++mt) {
        int row0 = mg * 32 + mt * 16 + qr;
        float mu0 = mus[row0],     rs0 = rss[row0];
        float mu1 = mus[row0 + 8], rs1 = rss[row0 + 8];
        #pragma unroll
        for (int nt = 0; nt < 8; ++nt) {
            int colb = ng * 64 + nt * 8 + ql * 2;
            float g0 = gs[colb], g1 = gs[colb + 1];
            float e0 = bes[colb], e1 = bes[colb + 1];
            float w0 = w3s[colb], w1 = w3s[colb + 1];
            float y;
            y = fmaxf((acc[mt][nt][0] - mu0) * rs0 * g0 + e0, 0.f); dots[mt][0] = fmaf(y, w0, dots[mt][0]);
            y = fmaxf((acc[mt][nt][1] - mu0) * rs0 * g1 + e1, 0.f); dots[mt][0] = fmaf(y, w1, dots[mt][0]);
            y = fmaxf((acc[mt][nt][2] - mu1) * rs1 * g0 + e0, 0.f); dots[mt][1] = fmaf(y, w0, dots[mt][1]);
            y = fmaxf((acc[mt][nt][3] - mu1) * rs1 * g1 + e1, 0.f); dots[mt][1] = fmaf(y, w1, dots[mt][1]);
        }
    }
    #pragma unroll
    for (int off = 1; off <= 2; off <<= 1)
        #pragma unroll
        for (int mt = 0; mt < 2; ++mt)
            #pragma unroll
            for (int ro = 0; ro < 2; ++ro)
                dots[mt][ro] += __shfl_xor_sync(0xffffffffu, dots[mt][ro], off);
    if (ql == 0) {
        #pragma unroll
        for (int mt = 0; mt < 2; ++mt)
            #pragma unroll
            for (int ro = 0; ro < 2; ++ro) {
                int row = mg * 32 + mt * 16 + ro * 8 + qr;
                sdot[ng * 128 + row] = dots[mt][ro];
            }
    }
    __syncthreads();

    if (tid < 128) {
        int eg = e_base + tid;
        if (eg < E) {
            float o = sdot[tid] + sdot[128 + tid] + sdot[256 + tid] + sdot[384 + tid] + b3[0];
            out[eg] = o;
        }
    }
}

extern "C" void kernel_launch(void* const* d_in, const int* in_sizes, int n_in,
                              void* d_out, int out_size) {
    const float* h_all  = (const float*)d_in[0];
    const int*   src    = (const int*)  d_in[1];
    const int*   dst    = (const int*)  d_in[2];
    const float* W1     = (const float*)d_in[3];
    const float* b1     = (const float*)d_in[4];
    const float* W3     = (const float*)d_in[5];
    const float* b3     = (const float*)d_in[6];
    const float* gamma2 = (const float*)d_in[7];
    const float* beta2  = (const float*)d_in[8];
    float* out = (float*)d_out;

    const int E = in_sizes[1];

    cudaFuncSetAttribute(fused_edge_mlp_mma,
                         cudaFuncAttributeMaxDynamicSharedMemorySize, SMEM_TOTAL);

    prep_w1<<<(HIDN * KDIM + 255) / 256, 256>>>(W1);

    int nb = (E + TILE_E - 1) / TILE_E;
    fused_edge_mlp_mma<<<nb, NTH, SMEM_TOTAL>>>(
        h_all, src, dst, b1, W3, b3, gamma2, beta2, out, E);
}

// round 6
// speedup vs baseline: 10.3362x; 1.9481x over previous
#include <cuda_runtime.h>
#include <cuda_fp16.h>
#include <cstdint>

// ---------------- problem constants ----------------
#define NNODES 50000
#define DHEAD  64
#define HIDN   256
#define KDIM   512
#define TILE_E 128           // edges per CTA
#define NTH    512           // 16 warps: 4 m-groups x 4 n-groups, warp tile 32x64
#define NCHUNK 16
#define KC     32            // K per chunk
#define BCHUNK_HALFS 8192    // 256 n * 32 k
#define ACHUNK_BYTES 8192    // 128 m * 32 k * 2B
#define BCHUNK_BYTES 16384

// ---------------- smem layout (bytes) ----------------
#define SM_SIDX  0                 // 128 ints
#define SM_DIDX  512
#define SM_B1    1024              // 256 f each
#define SM_G     2048
#define SM_BE    3072
#define SM_W3    4096
#define SM_SSUM  5120              // [4][128] f
#define SM_SSQ   7168
#define SM_SDOT  9216
#define SM_MUS   11264             // 128 f
#define SM_RSS   11776
#define SM_ABUF  12288             // 2 x 8KB
#define SM_BBUF  (SM_ABUF + 2 * ACHUNK_BYTES)   // 3 x 16KB
#define SMEM_TOTAL (SM_BBUF + 3 * BCHUNK_BYTES) // 77824

// W1 pre-packed per-chunk into m16n8k16 fp16 B-fragment order.
__device__ __half g_Bpack[NCHUNK * BCHUNK_HALFS];   // 256 KB

// ---------------- helpers ----------------
__device__ __forceinline__ uint32_t smem_u32(const void* p) {
    uint32_t a;
    asm("{ .reg .u64 t; cvta.to.shared.u64 t, %1; cvt.u32.u64 %0, t; }" : "=r"(a) : "l"(p));
    return a;
}
__device__ __forceinline__ float tanh_fast(float x) {
    float r;
    asm("tanh.approx.f32 %0, %1;" : "=f"(r) : "f"(x));
    return r;
}
__device__ __forceinline__ void cp16(uint32_t dst, const void* src) {
    asm volatile("cp.async.ca.shared.global [%0], [%1], 16;" :: "r"(dst), "l"(src));
}
__device__ __forceinline__ void cp_commit() {
    asm volatile("cp.async.commit_group;" ::: "memory");
}
template <int N>
__device__ __forceinline__ void cp_wait() {
    asm volatile("cp.async.wait_group %0;" :: "n"(N) : "memory");
}
__device__ __forceinline__ void mma_f16(float* c, const uint4& a, const uint2& b) {
    asm volatile(
        "mma.sync.aligned.m16n8k16.row.col.f32.f16.f16.f32 "
        "{%0,%1,%2,%3}, {%4,%5,%6,%7}, {%8,%9}, {%0,%1,%2,%3};"
        : "+f"(c[0]), "+f"(c[1]), "+f"(c[2]), "+f"(c[3])
        : "r"(a.x), "r"(a.y), "r"(a.z), "r"(a.w), "r"(b.x), "r"(b.y));
}

// ---------------- W1 prep: fp16 + fragment pack ----------------
// m16n8k16 B fragment (col-major): b0 holds k=2*(lane&3)+{0,1}, n=lane>>2;
// b1 holds k+8. Stored as uint2 blocks: [ (g*2+kt)*32 + lane ], g = (n>>6)*8 + ((n>>3)&7).
__global__ void prep_w1(const float* __restrict__ W1) {
    int i = blockIdx.x * blockDim.x + threadIdx.x;
    if (i >= HIDN * KDIM) return;
    int n = i >> 9;
    int k = i & 511;
    int c = k >> 5, kc = k & 31;
    int kt = kc >> 4, kk = kc & 15;
    int g = ((n >> 6) << 3) | ((n >> 3) & 7);
    int lane = ((n & 7) << 2) | ((kk >> 1) & 3);
    int breg = kk >> 3, lo = kk & 1;
    int idx = c * BCHUNK_HALFS + ((g * 2 + kt) * 32 + lane) * 4 + breg * 2 + lo;
    g_Bpack[idx] = __float2half(W1[i]);
}

// ---------------- fused kernel ----------------
__global__ __launch_bounds__(NTH, 1)
void fused_edge_mlp_f16(const float* __restrict__ h_all,
                        const int*   __restrict__ src,
                        const int*   __restrict__ dst,
                        const float* __restrict__ b1,
                        const float* __restrict__ W3,
                        const float* __restrict__ b3,
                        const float* __restrict__ gamma2,
                        const float* __restrict__ beta2,
                        float* __restrict__ out,
                        int E) {
    extern __shared__ char smem[];
    const uint32_t sb = smem_u32(smem);

    const int tid  = threadIdx.x;
    const int wid  = tid >> 5;
    const int lane = tid & 31;
    const int mg   = wid >> 2;      // m-group: rows mg*32 .. +31
    const int ng   = wid & 3;       // n-group: cols ng*64 .. +63
    const int e_base = blockIdx.x * TILE_E;

    int*   sidx = (int*)(smem + SM_SIDX);
    int*   didx = (int*)(smem + SM_DIDX);
    float* b1s  = (float*)(smem + SM_B1);
    float* gs   = (float*)(smem + SM_G);
    float* bes  = (float*)(smem + SM_BE);
    float* w3s  = (float*)(smem + SM_W3);
    float* ssum = (float*)(smem + SM_SSUM);
    float* ssq  = (float*)(smem + SM_SSQ);
    float* sdot = (float*)(smem + SM_SDOT);
    float* mus  = (float*)(smem + SM_MUS);
    float* rss  = (float*)(smem + SM_RSS);

    // B stages 0 and 1 in flight ASAP (no smem dependencies)
    #pragma unroll
    for (int s = 0; s < 2; ++s) {
        const __half* bsrc = g_Bpack + s * BCHUNK_HALFS;
        #pragma unroll
        for (int i = 0; i < 2; ++i)
            cp16(sb + SM_BBUF + s * BCHUNK_BYTES + (i * NTH + tid) * 16,
                 bsrc + (i * NTH + tid) * 8);
        cp_commit();
    }

    if (tid < TILE_E) {
        int eg = e_base + tid;
        if (eg >= E) eg = E - 1;
        sidx[tid] = src[eg];
        didx[tid] = dst[eg];
    }
    if (tid < HIDN) {
        b1s[tid] = b1[tid];
        gs[tid]  = gamma2[tid];
        bes[tid] = beta2[tid];
        w3s[tid] = W3[tid];
    }
    __syncthreads();

    float acc[2][8][4];
    #pragma unroll
    for (int mt = 0; mt < 2; ++mt)
        #pragma unroll
        for (int nt = 0; nt < 8; ++nt)
            #pragma unroll
            for (int j = 0; j < 4; ++j) acc[mt][nt][j] = 0.f;

    // gather A chunk 0 (l=0, src half, cc0=0)
    float4 pa[2];
    #pragma unroll
    for (int i = 0; i < 2; ++i) {
        int f = i * NTH + tid;
        int e = f >> 3, q = f & 7;
        pa[i] = *(const float4*)(h_all + (size_t)sidx[e] * DHEAD + q * 4);
    }
    // STS A(0) into buf 0
    {
        uint32_t* ab = (uint32_t*)(smem + SM_ABUF);
        #pragma unroll
        for (int i = 0; i < 2; ++i) {
            int f = i * NTH + tid;
            int e = f >> 3, q = f & 7;
            const float im = 0.1f;
            __half2 h2a = __floats2half2_rn(tanh_fast(pa[i].x * im), tanh_fast(pa[i].y * im));
            __half2 h2b = __floats2half2_rn(tanh_fast(pa[i].z * im), tanh_fast(pa[i].w * im));
            uint32_t u[2] = {*(uint32_t*)&h2a, *(uint32_t*)&h2b};
            int mgr = e >> 5, mt = (e >> 4) & 1, r = e & 15;
            #pragma unroll
            for (int p = 0; p < 2; ++p) {
                int kcp = 4 * q + 2 * p;
                int kt = kcp >> 4, kk = kcp & 15;
                int ln = ((r & 7) << 2) | ((kk >> 1) & 3);
                int areg = (r >> 3) | ((kk >> 3) << 1);
                ab[(((mgr * 2 + mt) * 2 + kt) * 32 + ln) * 4 + areg] = u[p];
            }
        }
    }
    // gather A chunk 1 (l=0, dst half, cc0=0)  [chunk 1: l=0, half=0, cc0=32]
    {
        const int cn = 1;
        const int l = cn >> 2, half = (cn >> 1) & 1, cc0 = (cn & 1) * KC;
        const int* ip = half ? didx : sidx;
        const float* hb = h_all + (size_t)l * (NNODES * DHEAD) + cc0;
        #pragma unroll
        for (int i = 0; i < 2; ++i) {
            int f = i * NTH + tid;
            int e = f >> 3, q = f & 7;
            pa[i] = *(const float4*)(hb + (size_t)ip[e] * DHEAD + q * 4);
        }
    }

    #pragma unroll 1
    for (int c = 0; c < NCHUNK; ++c) {
        if (c < NCHUNK - 1) cp_wait<1>(); else cp_wait<0>();
        __syncthreads();   // A(c) STS visible; buffers being overwritten are free

        // issue B(c+2) into slot (c+2)%3 (that slot was consumed at iter c-1)
        if (c < NCHUNK - 2) {
            const int s = (c + 2) % 3;
            const __half* bsrc = g_Bpack + (c + 2) * BCHUNK_HALFS;
            #pragma unroll
            for (int i = 0; i < 2; ++i)
                cp16(sb + SM_BBUF + s * BCHUNK_BYTES + (i * NTH + tid) * 16,
                     bsrc + (i * NTH + tid) * 8);
            cp_commit();
        }

        // STS A(c+1) from pa into buf (c+1)&1
        if (c < NCHUNK - 1) {
            const int cn = c + 1;
            const float im = 0.1f * (float)((cn >> 2) + 1);
            uint32_t* ab = (uint32_t*)(smem + SM_ABUF + (cn & 1) * ACHUNK_BYTES);
            #pragma unroll
            for (int i = 0; i < 2; ++i) {
                int f = i * NTH + tid;
                int e = f >> 3, q = f & 7;
                __half2 h2a = __floats2half2_rn(tanh_fast(pa[i].x * im), tanh_fast(pa[i].y * im));
                __half2 h2b = __floats2half2_rn(tanh_fast(pa[i].z * im), tanh_fast(pa[i].w * im));
                uint32_t u[2] = {*(uint32_t*)&h2a, *(uint32_t*)&h2b};
                int mgr = e >> 5, mt = (e >> 4) & 1, r = e & 15;
                #pragma unroll
                for (int p = 0; p < 2; ++p) {
                    int kcp = 4 * q + 2 * p;
                    int kt = kcp >> 4, kk = kcp & 15;
                    int ln = ((r & 7) << 2) | ((kk >> 1) & 3);
                    int areg = (r >> 3) | ((kk >> 3) << 1);
                    ab[(((mgr * 2 + mt) * 2 + kt) * 32 + ln) * 4 + areg] = u[p];
                }
            }
        }

        // gather A(c+2) -> pa (LDG latency hidden under MMA below)
        if (c < NCHUNK - 2) {
            const int cn = c + 2;
            const int l = cn >> 2, half = (cn >> 1) & 1, cc0 = (cn & 1) * KC;
            const int* ip = half ? didx : sidx;
            const float* hb = h_all + (size_t)l * (NNODES * DHEAD) + cc0;
            #pragma unroll
            for (int i = 0; i < 2; ++i) {
                int f = i * NTH + tid;
                int e = f >> 3, q = f & 7;
                pa[i] = *(const float4*)(hb + (size_t)ip[e] * DHEAD + q * 4);
            }
        }

        // ---- MMA on chunk c ----
        {
            const uint4* Ab = (const uint4*)(smem + SM_ABUF + (c & 1) * ACHUNK_BYTES);
            const uint2* Bb = (const uint2*)(smem + SM_BBUF + (c % 3) * BCHUNK_BYTES);
            #pragma unroll
            for (int kt = 0; kt < 2; ++kt) {
                uint2 bb[8];
                #pragma unroll
                for (int nt = 0; nt < 8; ++nt)
                    bb[nt] = Bb[(((ng * 8 + nt) * 2 + kt) * 32) + lane];
                uint4 aa[2];
                #pragma unroll
                for (int mt = 0; mt < 2; ++mt)
                    aa[mt] = Ab[(((mg * 2 + mt) * 2 + kt) * 32) + lane];
                #pragma unroll
                for (int mt = 0; mt < 2; ++mt)
                    #pragma unroll
                    for (int nt = 0; nt < 8; ++nt)
                        mma_f16(acc[mt][nt], aa[mt], bb[nt]);
            }
        }
    }

    // ---------------- epilogue ----------------
    const int qr = lane >> 2;   // row within 8-row group
    const int ql = lane & 3;    // col pair selector

    float sums[2][2] = {{0.f, 0.f}, {0.f, 0.f}};
    float sqs[2][2]  = {{0.f, 0.f}, {0.f, 0.f}};
    #pragma unroll
    for (int mt = 0; mt < 2; ++mt) {
        #pragma unroll
        for (int nt = 0; nt < 8; ++nt) {
            int colb = ng * 64 + nt * 8 + ql * 2;
            float b10 = b1s[colb], b11 = b1s[colb + 1];
            float v0 = acc[mt][nt][0] + b10;
            float v1 = acc[mt][nt][1] + b11;
            float v2 = acc[mt][nt][2] + b10;
            float v3 = acc[mt][nt][3] + b11;
            acc[mt][nt][0] = v0; acc[mt][nt][1] = v1;
            acc[mt][nt][2] = v2; acc[mt][nt][3] = v3;
            sums[mt][0] += v0 + v1;           sums[mt][1] += v2 + v3;
            sqs[mt][0] = fmaf(v0, v0, sqs[mt][0]); sqs[mt][0] = fmaf(v1, v1, sqs[mt][0]);
            sqs[mt][1] = fmaf(v2, v2, sqs[mt][1]); sqs[mt][1] = fmaf(v3, v3, sqs[mt][1]);
        }
    }
    #pragma unroll
    for (int off = 1; off <= 2; off <<= 1) {
        #pragma unroll
        for (int mt = 0; mt < 2; ++mt)
            #pragma unroll
            for (int ro = 0; ro < 2; ++ro) {
                sums[mt][ro] += __shfl_xor_sync(0xffffffffu, sums[mt][ro], off);
                sqs[mt][ro]  += __shfl_xor_sync(0xffffffffu, sqs[mt][ro], off);
            }
    }
    if (ql == 0) {
        #pragma unroll
        for (int mt = 0; mt < 2; ++mt)
            #pragma unroll
            for (int ro = 0; ro < 2; ++ro) {
                int row = mg * 32 + mt * 16 + ro * 8 + qr;
                ssum[ng * 128 + row] = sums[mt][ro];
                ssq[ng * 128 + row]  = sqs[mt][ro];
            }
    }
    __syncthreads();

    if (tid < 128) {
        float ts = ssum[tid] + ssum[128 + tid] + ssum[256 + tid] + ssum[384 + tid];
        float tq = ssq[tid]  + ssq[128 + tid]  + ssq[256 + tid]  + ssq[384 + tid];
        float mu  = ts * (1.f / 256.f);
        float var = tq * (1.f / 256.f) - mu * mu;
        mus[tid] = mu;
        rss[tid] = rsqrtf(var + 1e-5f);
    }
    __syncthreads();

    float dots[2][2] = {{0.f, 0.f}, {0.f, 0.f}};
    #pragma unroll
    for (int mt = 0; mt < 2; ++mt) {
        int row0 = mg * 32 + mt * 16 + qr;
        float mu0 = mus[row0],     rs0 = rss[row0];
        float mu1 = mus[row0 + 8], rs1 = rss[row0 + 8];
        #pragma unroll
        for (int nt = 0; nt < 8; ++nt) {
            int colb = ng * 64 + nt * 8 + ql * 2;
            float g0 = gs[colb], g1 = gs[colb + 1];
            float e0 = bes[colb], e1 = bes[colb + 1];
            float w0 = w3s[colb], w1 = w3s[colb + 1];
            float y;
            y = fmaxf((acc[mt][nt][0] - mu0) * rs0 * g0 + e0, 0.f); dots[mt][0] = fmaf(y, w0, dots[mt][0]);
            y = fmaxf((acc[mt][nt][1] - mu0) * rs0 * g1 + e1, 0.f); dots[mt][0] = fmaf(y, w1, dots[mt][0]);
            y = fmaxf((acc[mt][nt][2] - mu1) * rs1 * g0 + e0, 0.f); dots[mt][1] = fmaf(y, w0, dots[mt][1]);
            y = fmaxf((acc[mt][nt][3] - mu1) * rs1 * g1 + e1, 0.f); dots[mt][1] = fmaf(y, w1, dots[mt][1]);
        }
    }
    #pragma unroll
    for (int off = 1; off <= 2; off <<= 1)
        #pragma unroll
        for (int mt = 0; mt < 2; ++mt)
            #pragma unroll
            for (int ro = 0; ro < 2; ++ro)
                dots[mt][ro] += __shfl_xor_sync(0xffffffffu, dots[mt][ro], off);
    if (ql == 0) {
        #pragma unroll
        for (int mt = 0; mt < 2; ++mt)
            #pragma unroll
            for (int ro = 0; ro < 2; ++ro) {
                int row = mg * 32 + mt * 16 + ro * 8 + qr;
                sdot[ng * 128 + row] = dots[mt][ro];
            }
    }
    __syncthreads();

    if (tid < 128) {
        int eg = e_base + tid;
        if (eg < E) {
            out[eg] = sdot[tid] + sdot[128 + tid] + sdot[256 + tid] + sdot[384 + tid] + b3[0];
        }
    }
}

extern "C" void kernel_launch(void* const* d_in, const int* in_sizes, int n_in,
                              void* d_out, int out_size) {
    const float* h_all  = (const float*)d_in[0];
    const int*   src    = (const int*)  d_in[1];
    const int*   dst    = (const int*)  d_in[2];
    const float* W1     = (const float*)d_in[3];
    const float* b1     = (const float*)d_in[4];
    const float* W3     = (const float*)d_in[5];
    const float* b3     = (const float*)d_in[6];
    const float* gamma2 = (const float*)d_in[7];
    const float* beta2  = (const float*)d_in[8];
    float* out = (float*)d_out;

    const int E = in_sizes[1];

    cudaFuncSetAttribute(fused_edge_mlp_f16,
                         cudaFuncAttributeMaxDynamicSharedMemorySize, SMEM_TOTAL);

    prep_w1<<<(HIDN * KDIM + 255) / 256, 256>>>(W1);

    int nb = (E + TILE_E - 1) / TILE_E;
    fused_edge_mlp_f16<<<nb, NTH, SMEM_TOTAL>>>(
        h_all, src, dst, b1, W3, b3, gamma2, beta2, out, E);
}

// round 7
// speedup vs baseline: 11.6770x; 1.1297x over previous
#include <cuda_runtime.h>
#include <cuda_fp16.h>
#include <cstdint>

// ---------------- problem constants ----------------
#define NNODES 50000
#define DHEAD  64
#define HIDN   256
#define KDIM   512
#define TILE_E 64            // edges per CTA
#define NTH    256           // 8 warps: 2 m-groups x 4 n-groups, warp tile 32x64
#define NCHUNK 16
#define KC     32            // K per chunk
#define BCHUNK_HALFS 8192    // 256 n * 32 k
#define ACHUNK_BYTES 4096    // 64 m * 32 k * 2B
#define BCHUNK_BYTES 16384

// ---------------- smem layout (bytes) ----------------
#define SM_SIDX  0                 // 64 ints
#define SM_DIDX  256
#define SM_B1    512               // 256 f each
#define SM_G     1536
#define SM_BE    2560
#define SM_W3    3584
#define SM_SSUM  4608              // [4][64] f
#define SM_SSQ   5632
#define SM_SDOT  6656
#define SM_MUS   7680              // 64 f
#define SM_RSS   7936
#define SM_ABUF  8192              // 2 x 4KB
#define SM_BBUF  (SM_ABUF + 2 * ACHUNK_BYTES)   // 3 x 16KB
#define SMEM_TOTAL (SM_BBUF + 3 * BCHUNK_BYTES) // 65536 -> 2 CTAs = 128KB/SM

// W1 pre-packed per-chunk into m16n8k16 fp16 B-fragment order.
__device__ __half g_Bpack[NCHUNK * BCHUNK_HALFS];   // 256 KB

// ---------------- helpers ----------------
__device__ __forceinline__ uint32_t smem_u32(const void* p) {
    uint32_t a;
    asm("{ .reg .u64 t; cvta.to.shared.u64 t, %1; cvt.u32.u64 %0, t; }" : "=r"(a) : "l"(p));
    return a;
}
__device__ __forceinline__ float tanh_fast(float x) {
    float r;
    asm("tanh.approx.f32 %0, %1;" : "=f"(r) : "f"(x));
    return r;
}
__device__ __forceinline__ void cp16(uint32_t dst, const void* src) {
    asm volatile("cp.async.ca.shared.global [%0], [%1], 16;" :: "r"(dst), "l"(src));
}
__device__ __forceinline__ void cp_commit() {
    asm volatile("cp.async.commit_group;" ::: "memory");
}
template <int N>
__device__ __forceinline__ void cp_wait() {
    asm volatile("cp.async.wait_group %0;" :: "n"(N) : "memory");
}
__device__ __forceinline__ void mma_f16(float* c, const uint4& a, const uint2& b) {
    asm volatile(
        "mma.sync.aligned.m16n8k16.row.col.f32.f16.f16.f32 "
        "{%0,%1,%2,%3}, {%4,%5,%6,%7}, {%8,%9}, {%0,%1,%2,%3};"
        : "+f"(c[0]), "+f"(c[1]), "+f"(c[2]), "+f"(c[3])
        : "r"(a.x), "r"(a.y), "r"(a.z), "r"(a.w), "r"(b.x), "r"(b.y));
}

// ---------------- W1 prep: fp16 + fragment pack ----------------
// m16n8k16 B fragment (col-major): b0 holds k=2*(lane&3)+{0,1}, n=lane>>2;
// b1 holds k+8. Stored as uint2 blocks: [ (g*2+kt)*32 + lane ], g = (n>>6)*8 + ((n>>3)&7).
__global__ void prep_w1(const float* __restrict__ W1) {
    int i = blockIdx.x * blockDim.x + threadIdx.x;
    if (i >= HIDN * KDIM) return;
    int n = i >> 9;
    int k = i & 511;
    int c = k >> 5, kc = k & 31;
    int kt = kc >> 4, kk = kc & 15;
    int g = ((n >> 6) << 3) | ((n >> 3) & 7);
    int lane = ((n & 7) << 2) | ((kk >> 1) & 3);
    int breg = kk >> 3, lo = kk & 1;
    int idx = c * BCHUNK_HALFS + ((g * 2 + kt) * 32 + lane) * 4 + breg * 2 + lo;
    g_Bpack[idx] = __float2half(W1[i]);
}

// ---------------- fused kernel ----------------
__global__ __launch_bounds__(NTH, 2)
void fused_edge_mlp_f16(const float* __restrict__ h_all,
                        const int*   __restrict__ src,
                        const int*   __restrict__ dst,
                        const float* __restrict__ b1,
                        const float* __restrict__ W3,
                        const float* __restrict__ b3,
                        const float* __restrict__ gamma2,
                        const float* __restrict__ beta2,
                        float* __restrict__ out,
                        int E) {
    extern __shared__ char smem[];
    const uint32_t sb = smem_u32(smem);

    const int tid  = threadIdx.x;
    const int wid  = tid >> 5;
    const int lane = tid & 31;
    const int mg   = wid >> 2;      // m-group: rows mg*32 .. +31  (0..1)
    const int ng   = wid & 3;       // n-group: cols ng*64 .. +63
    const int e_base = blockIdx.x * TILE_E;

    int*   sidx = (int*)(smem + SM_SIDX);
    int*   didx = (int*)(smem + SM_DIDX);
    float* b1s  = (float*)(smem + SM_B1);
    float* gs   = (float*)(smem + SM_G);
    float* bes  = (float*)(smem + SM_BE);
    float* w3s  = (float*)(smem + SM_W3);
    float* ssum = (float*)(smem + SM_SSUM);
    float* ssq  = (float*)(smem + SM_SSQ);
    float* sdot = (float*)(smem + SM_SDOT);
    float* mus  = (float*)(smem + SM_MUS);
    float* rss  = (float*)(smem + SM_RSS);

    // B stages 0 and 1 in flight ASAP (no smem dependencies)
    #pragma unroll
    for (int s = 0; s < 2; ++s) {
        const __half* bsrc = g_Bpack + s * BCHUNK_HALFS;
        #pragma unroll
        for (int i = 0; i < 4; ++i)
            cp16(sb + SM_BBUF + s * BCHUNK_BYTES + (i * NTH + tid) * 16,
                 bsrc + (i * NTH + tid) * 8);
        cp_commit();
    }

    if (tid < TILE_E) {
        int eg = e_base + tid;
        if (eg >= E) eg = E - 1;
        sidx[tid] = src[eg];
        didx[tid] = dst[eg];
    }
    if (tid < HIDN) {
        b1s[tid] = b1[tid];
        gs[tid]  = gamma2[tid];
        bes[tid] = beta2[tid];
        w3s[tid] = W3[tid];
    }
    __syncthreads();

    float acc[2][8][4];
    #pragma unroll
    for (int mt = 0; mt < 2; ++mt)
        #pragma unroll
        for (int nt = 0; nt < 8; ++nt)
            #pragma unroll
            for (int j = 0; j < 4; ++j) acc[mt][nt][j] = 0.f;

    // gather A chunk 0 (l=0, src half, cc0=0): 64 edges x 8 float4 = 512 = 2*NTH
    float4 pa[2];
    #pragma unroll
    for (int i = 0; i < 2; ++i) {
        int f = i * NTH + tid;
        int e = f >> 3, q = f & 7;
        pa[i] = *(const float4*)(h_all + (size_t)sidx[e] * DHEAD + q * 4);
    }
    // STS A(0) into buf 0
    {
        uint32_t* ab = (uint32_t*)(smem + SM_ABUF);
        #pragma unroll
        for (int i = 0; i < 2; ++i) {
            int f = i * NTH + tid;
            int e = f >> 3, q = f & 7;
            const float im = 0.1f;
            __half2 h2a = __floats2half2_rn(tanh_fast(pa[i].x * im), tanh_fast(pa[i].y * im));
            __half2 h2b = __floats2half2_rn(tanh_fast(pa[i].z * im), tanh_fast(pa[i].w * im));
            uint32_t u[2] = {*(uint32_t*)&h2a, *(uint32_t*)&h2b};
            int mgr = e >> 5, mt = (e >> 4) & 1, r = e & 15;
            #pragma unroll
            for (int p = 0; p < 2; ++p) {
                int kcp = 4 * q + 2 * p;
                int kt = kcp >> 4, kk = kcp & 15;
                int ln = ((r & 7) << 2) | ((kk >> 1) & 3);
                int areg = (r >> 3) | ((kk >> 3) << 1);
                ab[(((mgr * 2 + mt) * 2 + kt) * 32 + ln) * 4 + areg] = u[p];
            }
        }
    }
    // gather A chunk 1
    {
        const int cn = 1;
        const int l = cn >> 2, half = (cn >> 1) & 1, cc0 = (cn & 1) * KC;
        const int* ip = half ? didx : sidx;
        const float* hb = h_all + (size_t)l * (NNODES * DHEAD) + cc0;
        #pragma unroll
        for (int i = 0; i < 2; ++i) {
            int f = i * NTH + tid;
            int e = f >> 3, q = f & 7;
            pa[i] = *(const float4*)(hb + (size_t)ip[e] * DHEAD + q * 4);
        }
    }

    #pragma unroll 1
    for (int c = 0; c < NCHUNK; ++c) {
        if (c < NCHUNK - 1) cp_wait<1>(); else cp_wait<0>();
        __syncthreads();   // A(c) STS visible; buffers being overwritten are free

        // issue B(c+2) into slot (c+2)%3 (consumed at iter c-1, safe past the barrier)
        if (c < NCHUNK - 2) {
            const int s = (c + 2) % 3;
            const __half* bsrc = g_Bpack + (c + 2) * BCHUNK_HALFS;
            #pragma unroll
            for (int i = 0; i < 4; ++i)
                cp16(sb + SM_BBUF + s * BCHUNK_BYTES + (i * NTH + tid) * 16,
                     bsrc + (i * NTH + tid) * 8);
            cp_commit();
        }

        // STS A(c+1) from pa into buf (c+1)&1
        if (c < NCHUNK - 1) {
            const int cn = c + 1;
            const float im = 0.1f * (float)((cn >> 2) + 1);
            uint32_t* ab = (uint32_t*)(smem + SM_ABUF + (cn & 1) * ACHUNK_BYTES);
            #pragma unroll
            for (int i = 0; i < 2; ++i) {
                int f = i * NTH + tid;
                int e = f >> 3, q = f & 7;
                __half2 h2a = __floats2half2_rn(tanh_fast(pa[i].x * im), tanh_fast(pa[i].y * im));
                __half2 h2b = __floats2half2_rn(tanh_fast(pa[i].z * im), tanh_fast(pa[i].w * im));
                uint32_t u[2] = {*(uint32_t*)&h2a, *(uint32_t*)&h2b};
                int mgr = e >> 5, mt = (e >> 4) & 1, r = e & 15;
                #pragma unroll
                for (int p = 0; p < 2; ++p) {
                    int kcp = 4 * q + 2 * p;
                    int kt = kcp >> 4, kk = kcp & 15;
                    int ln = ((r & 7) << 2) | ((kk >> 1) & 3);
                    int areg = (r >> 3) | ((kk >> 3) << 1);
                    ab[(((mgr * 2 + mt) * 2 + kt) * 32 + ln) * 4 + areg] = u[p];
                }
            }
        }

        // gather A(c+2) -> pa (LDG latency hidden under MMA below)
        if (c < NCHUNK - 2) {
            const int cn = c + 2;
            const int l = cn >> 2, half = (cn >> 1) & 1, cc0 = (cn & 1) * KC;
            const int* ip = half ? didx : sidx;
            const float* hb = h_all + (size_t)l * (NNODES * DHEAD) + cc0;
            #pragma unroll
            for (int i = 0; i < 2; ++i) {
                int f = i * NTH + tid;
                int e = f >> 3, q = f & 7;
                pa[i] = *(const float4*)(hb + (size_t)ip[e] * DHEAD + q * 4);
            }
        }

        // ---- MMA on chunk c ----
        {
            const uint4* Ab = (const uint4*)(smem + SM_ABUF + (c & 1) * ACHUNK_BYTES);
            const uint2* Bb = (const uint2*)(smem + SM_BBUF + (c % 3) * BCHUNK_BYTES);
            #pragma unroll
            for (int kt = 0; kt < 2; ++kt) {
                uint2 bb[8];
                #pragma unroll
                for (int nt = 0; nt < 8; ++nt)
                    bb[nt] = Bb[(((ng * 8 + nt) * 2 + kt) * 32) + lane];
                uint4 aa[2];
                #pragma unroll
                for (int mt = 0; mt < 2; ++mt)
                    aa[mt] = Ab[(((mg * 2 + mt) * 2 + kt) * 32) + lane];
                #pragma unroll
                for (int mt = 0; mt < 2; ++mt)
                    #pragma unroll
                    for (int nt = 0; nt < 8; ++nt)
                        mma_f16(acc[mt][nt], aa[mt], bb[nt]);
            }
        }
    }

    // ---------------- epilogue ----------------
    const int qr = lane >> 2;   // row within 8-row group
    const int ql = lane & 3;    // col pair selector

    float sums[2][2] = {{0.f, 0.f}, {0.f, 0.f}};
    float sqs[2][2]  = {{0.f, 0.f}, {0.f, 0.f}};
    #pragma unroll
    for (int mt = 0; mt < 2; ++mt) {
        #pragma unroll
        for (int nt = 0; nt < 8; ++nt) {
            int colb = ng * 64 + nt * 8 + ql * 2;
            float b10 = b1s[colb], b11 = b1s[colb + 1];
            float v0 = acc[mt][nt][0] + b10;
            float v1 = acc[mt][nt][1] + b11;
            float v2 = acc[mt][nt][2] + b10;
            float v3 = acc[mt][nt][3] + b11;
            acc[mt][nt][0] = v0; acc[mt][nt][1] = v1;
            acc[mt][nt][2] = v2; acc[mt][nt][3] = v3;
            sums[mt][0] += v0 + v1;           sums[mt][1] += v2 + v3;
            sqs[mt][0] = fmaf(v0, v0, sqs[mt][0]); sqs[mt][0] = fmaf(v1, v1, sqs[mt][0]);
            sqs[mt][1] = fmaf(v2, v2, sqs[mt][1]); sqs[mt][1] = fmaf(v3, v3, sqs[mt][1]);
        }
    }
    #pragma unroll
    for (int off = 1; off <= 2; off <<= 1) {
        #pragma unroll
        for (int mt = 0; mt < 2; ++mt)
            #pragma unroll
            for (int ro = 0; ro < 2; ++ro) {
                sums[mt][ro] += __shfl_xor_sync(0xffffffffu, sums[mt][ro], off);
                sqs[mt][ro]  += __shfl_xor_sync(0xffffffffu, sqs[mt][ro], off);
            }
    }
    if (ql == 0) {
        #pragma unroll
        for (int mt = 0; mt < 2; ++mt)
            #pragma unroll
            for (int ro = 0; ro < 2; ++ro) {
                int row = mg * 32 + mt * 16 + ro * 8 + qr;
                ssum[ng * 64 + row] = sums[mt][ro];
                ssq[ng * 64 + row]  = sqs[mt][ro];
            }
    }
    __syncthreads();

    if (tid < TILE_E) {
        float ts = ssum[tid] + ssum[64 + tid] + ssum[128 + tid] + ssum[192 + tid];
        float tq = ssq[tid]  + ssq[64 + tid]  + ssq[128 + tid]  + ssq[192 + tid];
        float mu  = ts * (1.f / 256.f);
        float var = tq * (1.f / 256.f) - mu * mu;
        mus[tid] = mu;
        rss[tid] = rsqrtf(var + 1e-5f);
    }
    __syncthreads();

    float dots[2][2] = {{0.f, 0.f}, {0.f, 0.f}};
    #pragma unroll
    for (int mt = 0; mt < 2; ++mt) {
        int row0 = mg * 32 + mt * 16 + qr;
        float mu0 = mus[row0],     rs0 = rss[row0];
        float mu1 = mus[row0 + 8], rs1 = rss[row0 + 8];
        #pragma unroll
        for (int nt = 0; nt < 8; ++nt) {
            int colb = ng * 64 + nt * 8 + ql * 2;
            float g0 = gs[colb], g1 = gs[colb + 1];
            float e0 = bes[colb], e1 = bes[colb + 1];
            float w0 = w3s[colb], w1 = w3s[colb + 1];
            float y;
            y = fmaxf((acc[mt][nt][0] - mu0) * rs0 * g0 + e0, 0.f); dots[mt][0] = fmaf(y, w0, dots[mt][0]);
            y = fmaxf((acc[mt][nt][1] - mu0) * rs0 * g1 + e1, 0.f); dots[mt][0] = fmaf(y, w1, dots[mt][0]);
            y = fmaxf((acc[mt][nt][2] - mu1) * rs1 * g0 + e0, 0.f); dots[mt][1] = fmaf(y, w0, dots[mt][1]);
            y = fmaxf((acc[mt][nt][3] - mu1) * rs1 * g1 + e1, 0.f); dots[mt][1] = fmaf(y, w1, dots[mt][1]);
        }
    }
    #pragma unroll
    for (int off = 1; off <= 2; off <<= 1)
        #pragma unroll
        for (int mt = 0; mt < 2; ++mt)
            #pragma unroll
            for (int ro = 0; ro < 2; ++ro)
                dots[mt][ro] += __shfl_xor_sync(0xffffffffu, dots[mt][ro], off);
    if (ql == 0) {
        #pragma unroll
        for (int mt = 0; mt < 2; ++mt)
            #pragma unroll
            for (int ro = 0; ro < 2; ++ro) {
                int row = mg * 32 + mt * 16 + ro * 8 + qr;
                sdot[ng * 64 + row] = dots[mt][ro];
            }
    }
    __syncthreads();

    if (tid < TILE_E) {
        int eg = e_base + tid;
        if (eg < E) {
            out[eg] = sdot[tid] + sdot[64 + tid] + sdot[128 + tid] + sdot[192 + tid] + b3[0];
        }
    }
}

extern "C" void kernel_launch(void* const* d_in, const int* in_sizes, int n_in,
                              void* d_out, int out_size) {
    const float* h_all  = (const float*)d_in[0];
    const int*   src    = (const int*)  d_in[1];
    const int*   dst    = (const int*)  d_in[2];
    const float* W1     = (const float*)d_in[3];
    const float* b1     = (const float*)d_in[4];
    const float* W3     = (const float*)d_in[5];
    const float* b3     = (const float*)d_in[6];
    const float* gamma2 = (const float*)d_in[7];
    const float* beta2  = (const float*)d_in[8];
    float* out = (float*)d_out;

    const int E = in_sizes[1];

    cudaFuncSetAttribute(fused_edge_mlp_f16,
                         cudaFuncAttributeMaxDynamicSharedMemorySize, SMEM_TOTAL);

    prep_w1<<<(HIDN * KDIM + 255) / 256, 256>>>(W1);

    int nb = (E + TILE_E - 1) / TILE_E;
    fused_edge_mlp_f16<<<nb, NTH, SMEM_TOTAL>>>(
        h_all, src, dst, b1, W3, b3, gamma2, beta2, out, E);
}